// round 7
// baseline (speedup 1.0000x reference)
#include <cuda_runtime.h>
#include <cstdint>

// BallPointQuery: per centroid, indices of up to 64 points within RADIUS
// (ascending), padded with first-neighbor index (0 if none).
// Shapes fixed by the problem: B=8, N=16384, M=1024, K=64.
//
// ROUND-7 FIX: output dtype is FLOAT32 (dataset canonicalization casts the
// reference's int32 indices to f32). All prior rounds wrote int32 bit
// patterns, which the comparator read as denormal floats (~1e-41 ~= 0),
// yielding rel_err == 1.000000 exactly regardless of kernel logic. Store
// (float)index — exact for idx < 2^24.
//
// One warp per centroid; ballot + prefix-popc ordered slot assignment;
// warp-uniform early exit at 64 hits.
// Numerics: expanded formula, each fp32 op individually rounded, NO FMA:
//   c2=(cx*cx+cy*cy)+cz*cz ; p2=(x*x+y*y)+z*z ; cp=((cx*x)+cy*y)+cz*z
//   d2=(c2+p2)-(2*cp) ; hit = d2 <= 0.04f

#define BB 8
#define NN 16384
#define MM 1024
#define KSAMP 64
#define TOTAL_WARPS (BB * MM)

__device__ int g_mode;  // 0 = float32 inputs, 1 = float64 inputs

__global__ void sniff_kernel(const void* pts_raw)
{
    if (threadIdx.x != 0 || blockIdx.x != 0) return;
    const float*  f = (const float*)pts_raw;
    const double* d = (const double*)pts_raw;
    int cf = 0, cd = 0;
    for (int i = 0; i < 1024; i++) {
        float v = f[i];
        if (v >= 0.0f && v <= 1.0f) cf++;
    }
    for (int i = 0; i < 512; i++) {
        double v = d[i];
        if (v >= 0.0 && v <= 1.0) cd++;
    }
    int mode = 0;
    if (cf >= 1020)      mode = 0;
    else if (cd >= 508)  mode = 1;
    g_mode = mode;
}

template <bool F64>
__device__ __forceinline__ void ballquery_body(
    const void* __restrict__ pts_raw,
    const void* __restrict__ cent_raw,
    float* __restrict__ out, int warp, int lane)
{
    const unsigned FULL = 0xffffffffu;
    int b = warp >> 10;
    int m = warp & (MM - 1);

    const float*  pf = (const float*)pts_raw;
    const double* pd = (const double*)pts_raw;
    const float*  cf = (const float*)cent_raw;
    const double* cd = (const double*)cent_raw;

    size_t pbase = (size_t)b * 3 * NN;
    size_t cbase = (size_t)b * 3 * MM;

    float cx, cy, cz;
    if (F64) {
        cx = (float)cd[cbase + m];
        cy = (float)cd[cbase + MM + m];
        cz = (float)cd[cbase + 2 * MM + m];
    } else {
        cx = __ldg(cf + cbase + m);
        cy = __ldg(cf + cbase + MM + m);
        cz = __ldg(cf + cbase + 2 * MM + m);
    }

    float c2 = __fadd_rn(__fadd_rn(__fmul_rn(cx, cx), __fmul_rn(cy, cy)),
                         __fmul_rn(cz, cz));
    const float r2 = 0.04f;  // jnp.float32(0.2*0.2)

    float* __restrict__ row = out + (size_t)warp * KSAMP;

    int base = 0;        // neighbors found so far (warp-uniform)
    int first_idx = -1;  // first neighbor index (warp-uniform once set)

    for (int n0 = 0; n0 < NN; n0 += 32) {
        int n = n0 + lane;
        float x, y, z;
        if (F64) {
            x = (float)pd[pbase + n];
            y = (float)pd[pbase + NN + n];
            z = (float)pd[pbase + 2 * NN + n];
        } else {
            x = __ldg(pf + pbase + n);
            y = __ldg(pf + pbase + NN + n);
            z = __ldg(pf + pbase + 2 * NN + n);
        }

        float p2 = __fadd_rn(__fadd_rn(__fmul_rn(x, x), __fmul_rn(y, y)),
                             __fmul_rn(z, z));
        float cp = __fadd_rn(__fadd_rn(__fmul_rn(cx, x), __fmul_rn(cy, y)),
                             __fmul_rn(cz, z));
        float d2 = __fsub_rn(__fadd_rn(c2, p2), __fmul_rn(2.0f, cp));

        bool hit = (d2 <= r2);
        unsigned mask = __ballot_sync(FULL, hit);
        if (mask) {
            if (first_idx < 0)
                first_idx = n0 + (__ffs(mask) - 1);
            if (hit) {
                int pos = base + __popc(mask & ((1u << lane) - 1u));
                if (pos < KSAMP) row[pos] = (float)n;   // FLOAT output
            }
            base += __popc(mask);
            if (base >= KSAMP) break;   // warp-uniform
        }
    }

    int cnt = base < KSAMP ? base : KSAMP;
    if (first_idx < 0) first_idx = 0;
    float pad = (float)first_idx;
    // Fill padding slots [cnt, KSAMP); also covers the zero-hit case.
    for (int s = cnt + lane; s < KSAMP; s += 32)
        row[s] = pad;
}

__global__ void __launch_bounds__(256)
ballquery_kernel(const void* __restrict__ pts_raw,
                 const void* __restrict__ cent_raw,
                 float* __restrict__ out)
{
    int warp = (int)((blockIdx.x * blockDim.x + threadIdx.x) >> 5);
    if (warp >= TOTAL_WARPS) return;
    int lane = (int)(threadIdx.x & 31);

    if (g_mode == 1)
        ballquery_body<true>(pts_raw, cent_raw, out, warp, lane);
    else
        ballquery_body<false>(pts_raw, cent_raw, out, warp, lane);
}

extern "C" void kernel_launch(void* const* d_in, const int* in_sizes, int n_in,
                              void* d_out, int out_size)
{
    // Binding: points = largest input, centroids = smallest (robust to
    // ordering and to element/byte size semantics).
    int ip = 0, ic = 0;
    for (int i = 1; i < n_in; i++) {
        if (in_sizes[i] > in_sizes[ip]) ip = i;
        if (in_sizes[i] < in_sizes[ic]) ic = i;
    }
    if (ip == ic && n_in >= 2) { ip = 0; ic = 1; }

    const void* pts  = d_in[ip];
    const void* cent = d_in[ic];
    float* out = (float*)d_out;   // [8, 1024, 64] float32 (indices as floats)

    sniff_kernel<<<1, 32>>>(pts);

    const int threads = 256;
    const int blocks  = (TOTAL_WARPS * 32) / threads;  // 1024
    ballquery_kernel<<<blocks, threads>>>(pts, cent, out);
}

// round 8
// speedup vs baseline: 2.3694x; 2.3694x over previous
#include <cuda_runtime.h>
#include <cstdint>

// BallPointQuery: per centroid, indices of up to 64 points within RADIUS
// (ascending), padded with first-neighbor index (0 if none).
// B=8, N=16384, M=1024, K=64. OUTPUT IS FLOAT32 (indices as floats) —
// confirmed by round-7 pass.
//
// Round 8: latency-bound baseline (issue 26%, all pipes <6%) -> widen the
// scan to 128 points/warp/iteration with float4 loads (3x LDG.128 instead
// of 12 scalar LDGs), 4x fewer ballot/branch rounds. Ordered slot
// assignment via per-lane 4-bit hitmask + 4 bit-ballots; order n = n0 +
// 4*lane + j is lane-major => ascending.
//
// Numerics: UNCHANGED per-point ops (bit-identical to the passing round):
//   c2=(cx*cx+cy*cy)+cz*cz ; p2=(x*x+y*y)+z*z ; cp=((cx*x)+cy*y)+cz*z
//   d2=(c2+p2)-(2*cp) ; hit = d2 <= 0.04f   (all __f*_rn, no FMA)

#define BB 8
#define NN 16384
#define MM 1024
#define KSAMP 64
#define TOTAL_WARPS (BB * MM)

__global__ void __launch_bounds__(128)
ballquery_kernel(const float* __restrict__ pts,    // [8, 3, 16384]
                 const float* __restrict__ cent,   // [8, 3, 1024]
                 float* __restrict__ out)          // [8, 1024, 64] f32
{
    const unsigned FULL = 0xffffffffu;
    int warp = (int)((blockIdx.x * blockDim.x + threadIdx.x) >> 5);
    int lane = (int)(threadIdx.x & 31);

    int b = warp >> 10;          // / 1024
    int m = warp & (MM - 1);

    const float* px = pts + (size_t)b * 3 * NN;
    const float* py = px + NN;
    const float* pz = py + NN;
    const float* cb = cent + (size_t)b * 3 * MM;

    float cx = __ldg(cb + m);
    float cy = __ldg(cb + MM + m);
    float cz = __ldg(cb + 2 * MM + m);

    float c2 = __fadd_rn(__fadd_rn(__fmul_rn(cx, cx), __fmul_rn(cy, cy)),
                         __fmul_rn(cz, cz));
    const float r2 = 0.04f;

    float* __restrict__ row = out + (size_t)warp * KSAMP;

    int base = 0;        // hits so far (warp-uniform)
    int first_idx = -1;  // first hit index (warp-uniform once set)
    const unsigned below = (1u << lane) - 1u;

    for (int n0 = 0; n0 < NN; n0 += 128) {
        int nl = n0 + 4 * lane;
        float4 X = __ldg((const float4*)(px + nl));
        float4 Y = __ldg((const float4*)(py + nl));
        float4 Z = __ldg((const float4*)(pz + nl));

        float xa[4] = {X.x, X.y, X.z, X.w};
        float ya[4] = {Y.x, Y.y, Y.z, Y.w};
        float za[4] = {Z.x, Z.y, Z.z, Z.w};

        unsigned h = 0;
        #pragma unroll
        for (int j = 0; j < 4; j++) {
            float x = xa[j], y = ya[j], z = za[j];
            float p2 = __fadd_rn(__fadd_rn(__fmul_rn(x, x), __fmul_rn(y, y)),
                                 __fmul_rn(z, z));
            float cp = __fadd_rn(__fadd_rn(__fmul_rn(cx, x), __fmul_rn(cy, y)),
                                 __fmul_rn(cz, z));
            float d2 = __fsub_rn(__fadd_rn(c2, p2), __fmul_rn(2.0f, cp));
            if (d2 <= r2) h |= (1u << j);
        }

        unsigned b0 = __ballot_sync(FULL, h & 1u);
        unsigned b1 = __ballot_sync(FULL, h & 2u);
        unsigned b2 = __ballot_sync(FULL, h & 4u);
        unsigned b3 = __ballot_sync(FULL, h & 8u);
        unsigned any = b0 | b1 | b2 | b3;   // bit l set iff lane l has a hit

        if (any) {
            if (first_idx < 0) {
                int l0 = __ffs(any) - 1;               // lowest lane with a hit
                unsigned h0 = __shfl_sync(FULL, h, l0);
                first_idx = n0 + 4 * l0 + (__ffs(h0) - 1);
            }
            // hits in lanes < lane (all j) precede all of this lane's hits
            int myPos = base
                      + __popc(b0 & below) + __popc(b1 & below)
                      + __popc(b2 & below) + __popc(b3 & below);
            #pragma unroll
            for (int j = 0; j < 4; j++) {
                if (h & (1u << j)) {
                    if (myPos < KSAMP)
                        row[myPos] = (float)(nl + j);
                    myPos++;
                }
            }
            base += __popc(b0) + __popc(b1) + __popc(b2) + __popc(b3);
            if (base >= KSAMP) break;   // warp-uniform
        }
    }

    int cnt = base < KSAMP ? base : KSAMP;
    if (first_idx < 0) first_idx = 0;
    float pad = (float)first_idx;
    for (int s = cnt + lane; s < KSAMP; s += 32)
        row[s] = pad;
}

extern "C" void kernel_launch(void* const* d_in, const int* in_sizes, int n_in,
                              void* d_out, int out_size)
{
    // points = largest input, centroids = smallest (robust binding).
    int ip = 0, ic = 0;
    for (int i = 1; i < n_in; i++) {
        if (in_sizes[i] > in_sizes[ip]) ip = i;
        if (in_sizes[i] < in_sizes[ic]) ic = i;
    }
    if (ip == ic && n_in >= 2) { ip = 0; ic = 1; }

    const float* pts  = (const float*)d_in[ip];
    const float* cent = (const float*)d_in[ic];
    float* out = (float*)d_out;

    // 8192 warps; 128-thread blocks (4 warps) for finer load balancing of
    // early-exit variance -> 2048 blocks.
    const int threads = 128;
    const int blocks  = (TOTAL_WARPS * 32) / threads;  // 2048
    ballquery_kernel<<<blocks, threads>>>(pts, cent, out);
}

// round 9
// speedup vs baseline: 3.0302x; 1.2789x over previous
#include <cuda_runtime.h>
#include <cstdint>

// BallPointQuery: per centroid, indices of up to 64 points within RADIUS
// (ascending), padded with first-neighbor index (0 if none).
// B=8, N=16384, M=1024, K=64. Output dtype: FLOAT32 (indices as floats).
//
// Round 9: epsilon-filtered hit test. The exact expanded formula
//   d2e = (c2+p2) - 2*cp   (each op __f*_rn, no FMA)   [round-8 decisions]
// and the cheap diff form d2a = dx^2+dy^2+dz^2 (FMA) differ by < 1.4e-6
// absolute. With EPS=1e-5:
//   d2a <= r2-EPS  => definite hit (matches exact)
//   d2a >  r2+EPS  => definite miss (matches exact)
//   else           => recompute exact (rare: ~2.5e-5 of points)
// => output decisions BIT-IDENTICAL to round 8 (rel_err must not change).
// Also widened to 256 points/warp/iter (6x LDG.128, 8 ballots).

#define BB 8
#define NN 16384
#define MM 1024
#define KSAMP 64
#define TOTAL_WARPS (BB * MM)

__device__ __forceinline__ float exact_d2(float c2, float cx, float cy, float cz,
                                          float x, float y, float z)
{
    float p2 = __fadd_rn(__fadd_rn(__fmul_rn(x, x), __fmul_rn(y, y)),
                         __fmul_rn(z, z));
    float cp = __fadd_rn(__fadd_rn(__fmul_rn(cx, x), __fmul_rn(cy, y)),
                         __fmul_rn(cz, z));
    return __fsub_rn(__fadd_rn(c2, p2), __fmul_rn(2.0f, cp));
}

__global__ void __launch_bounds__(128)
ballquery_kernel(const float* __restrict__ pts,    // [8, 3, 16384]
                 const float* __restrict__ cent,   // [8, 3, 1024]
                 float* __restrict__ out)          // [8, 1024, 64] f32
{
    const unsigned FULL = 0xffffffffu;
    int warp = (int)((blockIdx.x * blockDim.x + threadIdx.x) >> 5);
    int lane = (int)(threadIdx.x & 31);

    int b = warp >> 10;
    int m = warp & (MM - 1);

    const float* px = pts + (size_t)b * 3 * NN;
    const float* py = px + NN;
    const float* pz = py + NN;
    const float* cb = cent + (size_t)b * 3 * MM;

    float cx = __ldg(cb + m);
    float cy = __ldg(cb + MM + m);
    float cz = __ldg(cb + 2 * MM + m);

    float c2 = __fadd_rn(__fadd_rn(__fmul_rn(cx, cx), __fmul_rn(cy, cy)),
                         __fmul_rn(cz, cz));
    const float r2   = 0.04f;
    const float R2LO = 0.04f - 1e-5f;   // definite-hit threshold
    const float R2HI = 0.04f + 1e-5f;   // definite-miss threshold

    float* __restrict__ row = out + (size_t)warp * KSAMP;

    int base = 0;        // hits so far (warp-uniform)
    int first_idx = -1;  // first hit index (warp-uniform once set)
    const unsigned below = (1u << lane) - 1u;

    for (int n0 = 0; n0 < NN; n0 += 256) {
        int nl = n0 + 8 * lane;
        float4 X0 = __ldg((const float4*)(px + nl));
        float4 X1 = __ldg((const float4*)(px + nl + 4));
        float4 Y0 = __ldg((const float4*)(py + nl));
        float4 Y1 = __ldg((const float4*)(py + nl + 4));
        float4 Z0 = __ldg((const float4*)(pz + nl));
        float4 Z1 = __ldg((const float4*)(pz + nl + 4));

        float xa[8] = {X0.x, X0.y, X0.z, X0.w, X1.x, X1.y, X1.z, X1.w};
        float ya[8] = {Y0.x, Y0.y, Y0.z, Y0.w, Y1.x, Y1.y, Y1.z, Y1.w};
        float za[8] = {Z0.x, Z0.y, Z0.z, Z0.w, Z1.x, Z1.y, Z1.z, Z1.w};

        unsigned h = 0, band = 0;
        #pragma unroll
        for (int j = 0; j < 8; j++) {
            float dx = __fsub_rn(xa[j], cx);
            float dy = __fsub_rn(ya[j], cy);
            float dz = __fsub_rn(za[j], cz);
            float d2a = __fmaf_rn(dz, dz, __fmaf_rn(dy, dy, __fmul_rn(dx, dx)));
            if (d2a <= R2HI) {
                if (d2a <= R2LO) h |= (1u << j);
                else             band |= (1u << j);
            }
        }

        // Rare borderline points: resolve with the exact round-8 formula.
        if (__ballot_sync(FULL, band != 0u)) {
            #pragma unroll
            for (int j = 0; j < 8; j++) {
                if (band & (1u << j)) {
                    float d2e = exact_d2(c2, cx, cy, cz, xa[j], ya[j], za[j]);
                    if (d2e <= r2) h |= (1u << j);
                }
            }
        }

        unsigned b0 = __ballot_sync(FULL, h & 1u);
        unsigned b1 = __ballot_sync(FULL, h & 2u);
        unsigned b2 = __ballot_sync(FULL, h & 4u);
        unsigned b3 = __ballot_sync(FULL, h & 8u);
        unsigned b4 = __ballot_sync(FULL, h & 16u);
        unsigned b5 = __ballot_sync(FULL, h & 32u);
        unsigned b6 = __ballot_sync(FULL, h & 64u);
        unsigned b7 = __ballot_sync(FULL, h & 128u);
        unsigned any = b0 | b1 | b2 | b3 | b4 | b5 | b6 | b7;

        if (any) {
            if (first_idx < 0) {
                int l0 = __ffs(any) - 1;
                unsigned h0 = __shfl_sync(FULL, h, l0);
                first_idx = n0 + 8 * l0 + (__ffs(h0) - 1);
            }
            // index = n0 + 8*lane + j is lane-major: all hits of lanes < me
            // precede all of mine.
            int myPos = base
                      + __popc(b0 & below) + __popc(b1 & below)
                      + __popc(b2 & below) + __popc(b3 & below)
                      + __popc(b4 & below) + __popc(b5 & below)
                      + __popc(b6 & below) + __popc(b7 & below);
            #pragma unroll
            for (int j = 0; j < 8; j++) {
                if (h & (1u << j)) {
                    if (myPos < KSAMP)
                        row[myPos] = (float)(nl + j);
                    myPos++;
                }
            }
            base += __popc(b0) + __popc(b1) + __popc(b2) + __popc(b3)
                  + __popc(b4) + __popc(b5) + __popc(b6) + __popc(b7);
            if (base >= KSAMP) break;   // warp-uniform
        }
    }

    int cnt = base < KSAMP ? base : KSAMP;
    if (first_idx < 0) first_idx = 0;
    float pad = (float)first_idx;
    for (int s = cnt + lane; s < KSAMP; s += 32)
        row[s] = pad;
}

extern "C" void kernel_launch(void* const* d_in, const int* in_sizes, int n_in,
                              void* d_out, int out_size)
{
    // points = largest input, centroids = smallest (robust binding).
    int ip = 0, ic = 0;
    for (int i = 1; i < n_in; i++) {
        if (in_sizes[i] > in_sizes[ip]) ip = i;
        if (in_sizes[i] < in_sizes[ic]) ic = i;
    }
    if (ip == ic && n_in >= 2) { ip = 0; ic = 1; }

    const float* pts  = (const float*)d_in[ip];
    const float* cent = (const float*)d_in[ic];
    float* out = (float*)d_out;

    const int threads = 128;
    const int blocks  = (TOTAL_WARPS * 32) / threads;  // 2048
    ballquery_kernel<<<blocks, threads>>>(pts, cent, out);
}

// round 10
// speedup vs baseline: 3.1580x; 1.0422x over previous
#include <cuda_runtime.h>
#include <cstdint>

// BallPointQuery: per centroid, indices of up to 64 points within RADIUS
// (ascending), padded with first-neighbor index (0 if none).
// B=8, N=16384, M=1024, K=64. Output dtype: FLOAT32 (indices as floats).
//
// Round 10:
//  - packed f32x2 distance math (PTX add/mul/fma.rn.f32x2): 2 points/inst
//  - slot assignment via single shfl inclusive scan of popc(h) instead of
//    8 ballots + 16 popc (lane-major order preserved)
//  - empty-iteration fast path (helps tail warps scanning sparse regions)
//  - eps-filtered decision identical to rounds 8/9:
//      d2a (fma diff-form) vs band +-1e-5 around r2=0.04; borderline points
//      recomputed with the exact expanded formula (per-op rn, no FMA)
//    => rel_err must remain exactly 4.700719e-4.

#define BB 8
#define NN 16384
#define MM 1024
#define KSAMP 64
#define TOTAL_WARPS (BB * MM)

typedef unsigned long long ull;

#define PACK2(out, lo, hi) \
    asm("mov.b64 %0, {%1, %2};" : "=l"(out) : "f"(lo), "f"(hi))
#define UNPACK2(lo, hi, in) \
    asm("mov.b64 {%0, %1}, %2;" : "=f"(lo), "=f"(hi) : "l"(in))
#define ADDX2(out, a, b) \
    asm("add.rn.f32x2 %0, %1, %2;" : "=l"(out) : "l"(a), "l"(b))
#define MULX2(out, a, b) \
    asm("mul.rn.f32x2 %0, %1, %2;" : "=l"(out) : "l"(a), "l"(b))
#define FMAX2(out, a, b, c) \
    asm("fma.rn.f32x2 %0, %1, %2, %3;" : "=l"(out) : "l"(a), "l"(b), "l"(c))

__device__ __forceinline__ float exact_d2(float c2, float cx, float cy, float cz,
                                          float x, float y, float z)
{
    float p2 = __fadd_rn(__fadd_rn(__fmul_rn(x, x), __fmul_rn(y, y)),
                         __fmul_rn(z, z));
    float cp = __fadd_rn(__fadd_rn(__fmul_rn(cx, x), __fmul_rn(cy, y)),
                         __fmul_rn(cz, z));
    return __fsub_rn(__fadd_rn(c2, p2), __fmul_rn(2.0f, cp));
}

__global__ void __launch_bounds__(64)
ballquery_kernel(const float* __restrict__ pts,    // [8, 3, 16384]
                 const float* __restrict__ cent,   // [8, 3, 1024]
                 float* __restrict__ out)          // [8, 1024, 64] f32
{
    const unsigned FULL = 0xffffffffu;
    int warp = (int)((blockIdx.x * blockDim.x + threadIdx.x) >> 5);
    int lane = (int)(threadIdx.x & 31);

    int b = warp >> 10;
    int m = warp & (MM - 1);

    const float* px = pts + (size_t)b * 3 * NN;
    const float* py = px + NN;
    const float* pz = py + NN;
    const float* cb = cent + (size_t)b * 3 * MM;

    float cx = __ldg(cb + m);
    float cy = __ldg(cb + MM + m);
    float cz = __ldg(cb + 2 * MM + m);

    float c2 = __fadd_rn(__fadd_rn(__fmul_rn(cx, cx), __fmul_rn(cy, cy)),
                         __fmul_rn(cz, cz));
    const float r2   = 0.04f;
    const float R2LO = 0.04f - 1e-5f;
    const float R2HI = 0.04f + 1e-5f;

    ull ncx2, ncy2, ncz2;                 // packed (-c, -c)
    {
        float nx = -cx, ny = -cy, nz = -cz;
        PACK2(ncx2, nx, nx);
        PACK2(ncy2, ny, ny);
        PACK2(ncz2, nz, nz);
    }

    float* __restrict__ row = out + (size_t)warp * KSAMP;

    int base = 0;        // hits so far (warp-uniform)
    int first_idx = -1;  // first hit index (warp-uniform once set)

    for (int n0 = 0; n0 < NN; n0 += 256) {
        int nl = n0 + 8 * lane;
        float4 X0 = __ldg((const float4*)(px + nl));
        float4 X1 = __ldg((const float4*)(px + nl + 4));
        float4 Y0 = __ldg((const float4*)(py + nl));
        float4 Y1 = __ldg((const float4*)(py + nl + 4));
        float4 Z0 = __ldg((const float4*)(pz + nl));
        float4 Z1 = __ldg((const float4*)(pz + nl + 4));

        float xa[8] = {X0.x, X0.y, X0.z, X0.w, X1.x, X1.y, X1.z, X1.w};
        float ya[8] = {Y0.x, Y0.y, Y0.z, Y0.w, Y1.x, Y1.y, Y1.z, Y1.w};
        float za[8] = {Z0.x, Z0.y, Z0.z, Z0.w, Z1.x, Z1.y, Z1.z, Z1.w};

        unsigned h = 0, band = 0;
        #pragma unroll
        for (int p = 0; p < 4; p++) {
            ull X, Y, Z, dx, dy, dz, s;
            PACK2(X, xa[2*p], xa[2*p+1]);
            PACK2(Y, ya[2*p], ya[2*p+1]);
            PACK2(Z, za[2*p], za[2*p+1]);
            ADDX2(dx, X, ncx2);
            ADDX2(dy, Y, ncy2);
            ADDX2(dz, Z, ncz2);
            MULX2(s, dx, dx);
            FMAX2(s, dy, dy, s);
            FMAX2(s, dz, dz, s);
            float d0, d1;
            UNPACK2(d0, d1, s);
            if (d0 <= R2HI) { if (d0 <= R2LO) h |= 1u << (2*p);   else band |= 1u << (2*p); }
            if (d1 <= R2HI) { if (d1 <= R2LO) h |= 1u << (2*p+1); else band |= 1u << (2*p+1); }
        }

        // Rare borderline points: resolve with the exact expanded formula.
        if (__ballot_sync(FULL, band != 0u)) {
            #pragma unroll
            for (int j = 0; j < 8; j++) {
                if (band & (1u << j)) {
                    float d2e = exact_d2(c2, cx, cy, cz, xa[j], ya[j], za[j]);
                    if (d2e <= r2) h |= (1u << j);
                }
            }
        }

        unsigned hb = __ballot_sync(FULL, h != 0u);
        if (!hb) continue;                 // warp-uniform: empty iteration

        if (first_idx < 0) {
            int l0 = __ffs(hb) - 1;
            unsigned h0 = __shfl_sync(FULL, h, l0);
            first_idx = n0 + 8 * l0 + (__ffs(h0) - 1);
        }

        // Inclusive shfl scan of per-lane hit counts (lane-major order).
        int cnt = __popc(h);
        int inc = cnt;
        #pragma unroll
        for (int off = 1; off < 32; off <<= 1) {
            int v = __shfl_up_sync(FULL, inc, off);
            if (lane >= off) inc += v;
        }
        int total = __shfl_sync(FULL, inc, 31);
        int myPos = base + inc - cnt;

        #pragma unroll
        for (int j = 0; j < 8; j++) {
            if (h & (1u << j)) {
                if (myPos < KSAMP)
                    row[myPos] = (float)(nl + j);
                myPos++;
            }
        }
        base += total;
        if (base >= KSAMP) break;          // warp-uniform
    }

    int cnt = base < KSAMP ? base : KSAMP;
    if (first_idx < 0) first_idx = 0;
    float pad = (float)first_idx;
    for (int s = cnt + lane; s < KSAMP; s += 32)
        row[s] = pad;
}

extern "C" void kernel_launch(void* const* d_in, const int* in_sizes, int n_in,
                              void* d_out, int out_size)
{
    // points = largest input, centroids = smallest (robust binding).
    int ip = 0, ic = 0;
    for (int i = 1; i < n_in; i++) {
        if (in_sizes[i] > in_sizes[ip]) ip = i;
        if (in_sizes[i] < in_sizes[ic]) ic = i;
    }
    if (ip == ic && n_in >= 2) { ip = 0; ic = 1; }

    const float* pts  = (const float*)d_in[ip];
    const float* cent = (const float*)d_in[ic];
    float* out = (float*)d_out;

    // 64-thread blocks (2 warps) -> 4096 blocks: finer drain granularity
    // for the early-exit variance.
    const int threads = 64;
    const int blocks  = (TOTAL_WARPS * 32) / threads;  // 4096
    ballquery_kernel<<<blocks, threads>>>(pts, cent, out);
}

// round 11
// speedup vs baseline: 3.1775x; 1.0062x over previous
#include <cuda_runtime.h>
#include <cstdint>

// BallPointQuery: per centroid, indices of up to 64 points within RADIUS
// (ascending), padded with first-neighbor index (0 if none).
// B=8, N=16384, M=1024, K=64. Output dtype: FLOAT32 (indices as floats).
//
// Round 11:
//  - persistent warp-level WORK STEALING (global atomic counter) to erase
//    early-exit drain imbalance / wave structure
//  - DOUBLE-BUFFERED chunk prefetch: next iteration's 6x LDG.128 issue
//    before current iteration's compute -> memory latency hidden by ILP
//  - unchanged hit decisions (eps-band 1e-5 around r2 + exact expanded
//    formula fallback) => rel_err must remain exactly 4.700719e-4.

#define BB 8
#define NN 16384
#define MM 1024
#define KSAMP 64
#define TOTAL_WARPS (BB * MM)

typedef unsigned long long ull;

#define PACK2(out, lo, hi) \
    asm("mov.b64 %0, {%1, %2};" : "=l"(out) : "f"(lo), "f"(hi))
#define UNPACK2(lo, hi, in) \
    asm("mov.b64 {%0, %1}, %2;" : "=f"(lo), "=f"(hi) : "l"(in))
#define ADDX2(out, a, b) \
    asm("add.rn.f32x2 %0, %1, %2;" : "=l"(out) : "l"(a), "l"(b))
#define MULX2(out, a, b) \
    asm("mul.rn.f32x2 %0, %1, %2;" : "=l"(out) : "l"(a), "l"(b))
#define FMAX2(out, a, b, c) \
    asm("fma.rn.f32x2 %0, %1, %2, %3;" : "=l"(out) : "l"(a), "l"(b), "l"(c))

__device__ unsigned g_ctr;

__global__ void reset_ctr_kernel() { g_ctr = 0u; }

__device__ __forceinline__ float exact_d2(float c2, float cx, float cy, float cz,
                                          float x, float y, float z)
{
    float p2 = __fadd_rn(__fadd_rn(__fmul_rn(x, x), __fmul_rn(y, y)),
                         __fmul_rn(z, z));
    float cp = __fadd_rn(__fadd_rn(__fmul_rn(cx, x), __fmul_rn(cy, y)),
                         __fmul_rn(cz, z));
    return __fsub_rn(__fadd_rn(c2, p2), __fmul_rn(2.0f, cp));
}

__global__ void __launch_bounds__(128)
ballquery_kernel(const float* __restrict__ pts,    // [8, 3, 16384]
                 const float* __restrict__ cent,   // [8, 3, 1024]
                 float* __restrict__ out)          // [8, 1024, 64] f32
{
    const unsigned FULL = 0xffffffffu;
    int lane = (int)(threadIdx.x & 31);

    const float r2   = 0.04f;
    const float R2LO = 0.04f - 1e-5f;
    const float R2HI = 0.04f + 1e-5f;

    for (;;) {
        // ── steal next centroid ──
        unsigned widx;
        if (lane == 0) widx = atomicAdd(&g_ctr, 1u);
        widx = __shfl_sync(FULL, widx, 0);
        if (widx >= TOTAL_WARPS) return;

        int b = (int)(widx >> 10);
        int m = (int)(widx & (MM - 1));

        const float* px = pts + (size_t)b * 3 * NN;
        const float* py = px + NN;
        const float* pz = py + NN;
        const float* cb = cent + (size_t)b * 3 * MM;

        float cx = __ldg(cb + m);
        float cy = __ldg(cb + MM + m);
        float cz = __ldg(cb + 2 * MM + m);

        float c2 = __fadd_rn(__fadd_rn(__fmul_rn(cx, cx), __fmul_rn(cy, cy)),
                             __fmul_rn(cz, cz));

        ull ncx2, ncy2, ncz2;
        {
            float nx = -cx, ny = -cy, nz = -cz;
            PACK2(ncx2, nx, nx);
            PACK2(ncy2, ny, ny);
            PACK2(ncz2, nz, nz);
        }

        float* __restrict__ row = out + (size_t)widx * KSAMP;

        int base = 0;
        int first_idx = -1;

        // ── double-buffered scan ──
        int nl = 8 * lane;
        float4 X0 = __ldg((const float4*)(px + nl));
        float4 X1 = __ldg((const float4*)(px + nl + 4));
        float4 Y0 = __ldg((const float4*)(py + nl));
        float4 Y1 = __ldg((const float4*)(py + nl + 4));
        float4 Z0 = __ldg((const float4*)(pz + nl));
        float4 Z1 = __ldg((const float4*)(pz + nl + 4));

        for (int n0 = 0;;) {
            int n1 = n0 + 256;
            bool more = (n1 < NN);
            // prefetch next chunk (independent of current compute)
            float4 nX0, nX1, nY0, nY1, nZ0, nZ1;
            if (more) {
                int nn = n1 + 8 * lane;
                nX0 = __ldg((const float4*)(px + nn));
                nX1 = __ldg((const float4*)(px + nn + 4));
                nY0 = __ldg((const float4*)(py + nn));
                nY1 = __ldg((const float4*)(py + nn + 4));
                nZ0 = __ldg((const float4*)(pz + nn));
                nZ1 = __ldg((const float4*)(pz + nn + 4));
            }

            float xa[8] = {X0.x, X0.y, X0.z, X0.w, X1.x, X1.y, X1.z, X1.w};
            float ya[8] = {Y0.x, Y0.y, Y0.z, Y0.w, Y1.x, Y1.y, Y1.z, Y1.w};
            float za[8] = {Z0.x, Z0.y, Z0.z, Z0.w, Z1.x, Z1.y, Z1.z, Z1.w};

            unsigned h = 0, band = 0;
            #pragma unroll
            for (int p = 0; p < 4; p++) {
                ull X, Y, Z, dx, dy, dz, s;
                PACK2(X, xa[2*p], xa[2*p+1]);
                PACK2(Y, ya[2*p], ya[2*p+1]);
                PACK2(Z, za[2*p], za[2*p+1]);
                ADDX2(dx, X, ncx2);
                ADDX2(dy, Y, ncy2);
                ADDX2(dz, Z, ncz2);
                MULX2(s, dx, dx);
                FMAX2(s, dy, dy, s);
                FMAX2(s, dz, dz, s);
                float d0, d1;
                UNPACK2(d0, d1, s);
                if (d0 <= R2HI) { if (d0 <= R2LO) h |= 1u << (2*p);   else band |= 1u << (2*p); }
                if (d1 <= R2HI) { if (d1 <= R2LO) h |= 1u << (2*p+1); else band |= 1u << (2*p+1); }
            }

            if (__ballot_sync(FULL, band != 0u)) {
                #pragma unroll
                for (int j = 0; j < 8; j++) {
                    if (band & (1u << j)) {
                        float d2e = exact_d2(c2, cx, cy, cz, xa[j], ya[j], za[j]);
                        if (d2e <= r2) h |= (1u << j);
                    }
                }
            }

            unsigned hb = __ballot_sync(FULL, h != 0u);
            if (hb) {
                int base_n = n0 + 8 * lane;
                if (first_idx < 0) {
                    int l0 = __ffs(hb) - 1;
                    unsigned h0 = __shfl_sync(FULL, h, l0);
                    first_idx = n0 + 8 * l0 + (__ffs(h0) - 1);
                }
                int cnt = __popc(h);
                int inc = cnt;
                #pragma unroll
                for (int off = 1; off < 32; off <<= 1) {
                    int v = __shfl_up_sync(FULL, inc, off);
                    if (lane >= off) inc += v;
                }
                int total = __shfl_sync(FULL, inc, 31);
                int myPos = base + inc - cnt;
                #pragma unroll
                for (int j = 0; j < 8; j++) {
                    if (h & (1u << j)) {
                        if (myPos < KSAMP)
                            row[myPos] = (float)(base_n + j);
                        myPos++;
                    }
                }
                base += total;
                if (base >= KSAMP) break;   // warp-uniform
            }

            if (!more) break;
            n0 = n1;
            X0 = nX0; X1 = nX1; Y0 = nY0; Y1 = nY1; Z0 = nZ0; Z1 = nZ1;
        }

        int cnt = base < KSAMP ? base : KSAMP;
        if (first_idx < 0) first_idx = 0;
        float pad = (float)first_idx;
        for (int s = cnt + lane; s < KSAMP; s += 32)
            row[s] = pad;
    }
}

extern "C" void kernel_launch(void* const* d_in, const int* in_sizes, int n_in,
                              void* d_out, int out_size)
{
    // points = largest input, centroids = smallest (robust binding).
    int ip = 0, ic = 0;
    for (int i = 1; i < n_in; i++) {
        if (in_sizes[i] > in_sizes[ip]) ip = i;
        if (in_sizes[i] < in_sizes[ic]) ic = i;
    }
    if (ip == ic && n_in >= 2) { ip = 0; ic = 1; }

    const float* pts  = (const float*)d_in[ip];
    const float* cent = (const float*)d_in[ic];
    float* out = (float*)d_out;

    reset_ctr_kernel<<<1, 1>>>();

    // Persistent-ish grid: 1184 blocks x 4 warps = 4736 warps stealing
    // 8192 centroids (~1.7 each) -> tight load balance, no wave cliffs.
    const int threads = 128;
    const int blocks  = 1184;
    ballquery_kernel<<<blocks, threads>>>(pts, cent, out);
}